// round 14
// baseline (speedup 1.0000x reference)
#include <cuda_runtime.h>
#include <cuda_fp16.h>

// Problem constants
#define BB   2
#define SS   2048
#define DD   1024
#define HH   16
#define HDIM 64
#define MROWS (BB * SS)           // 4096
#define QKV_E (3 * DD)            // 3072
#define SCALE 0.125f              // 1/sqrt(64)
#define QSC   (0.125f * 1.4426950408889634f)   // SCALE * log2(e)
#define ONESH2 0x3C003C00u        // half2(1.0, 1.0)

// Scratch (device globals per harness allocation rules)
__device__ __align__(16) __half g_xhi[MROWS * DD];
__device__ __align__(16) __half g_wqh[QKV_E * DD];
__device__ __align__(16) __half g_woh[DD * DD];
__device__ __align__(16) __half g_ohi[MROWS * DD];
#define QKVN (BB * HH * SS * HDIM)
__device__ __align__(16) __half g_qh[QKVN];
__device__ __align__(16) __half g_kh[QKVN];
__device__ __align__(16) __half g_vh[QKVN];

__device__ __forceinline__ unsigned smem_u32(const void* p) {
    unsigned a;
    asm("{ .reg .u64 t; cvta.to.shared.u64 t, %1; cvt.u32.u64 %0, t; }"
        : "=r"(a) : "l"(p));
    return a;
}
__device__ __forceinline__ float ex2(float x) {
    float r;
    asm("ex2.approx.f32 %0, %1;" : "=f"(r) : "f"(x));
    return r;
}
// half2 exp2 of packed (a,b) -> single MUFU op
__device__ __forceinline__ unsigned h2ex2(float a, float b) {
    __half2 t = __floats2half2_rn(a, b);
    unsigned r;
    asm("ex2.approx.f16x2 %0, %1;" : "=r"(r) : "r"(*(unsigned*)&t));
    return r;
}

// ---------------------------------------------------------------------------
// Fused splits: x, w_qkv, w_out -> fp16 (round-to-nearest)
// ---------------------------------------------------------------------------
#define N4X (MROWS * DD / 4)      // 1048576
#define N4Q (QKV_E * DD / 4)      // 786432
#define N4W (DD * DD / 4)         // 262144
#define N4TOT (N4X + N4Q + N4W)   // 2097152

__global__ __launch_bounds__(256) void split_all(
    const float* __restrict__ x, const float* __restrict__ wq,
    const float* __restrict__ wo,
    __half* __restrict__ xhi, __half* __restrict__ wqh,
    __half* __restrict__ woh)
{
    int i = blockIdx.x * blockDim.x + threadIdx.x;
    if (i >= N4TOT) return;
    const float* src;
    __half* dst;
    int j;
    if (i < N4X)            { j = i;             src = x;  dst = xhi; }
    else if (i < N4X + N4Q) { j = i - N4X;       src = wq; dst = wqh; }
    else                    { j = i - N4X - N4Q; src = wo; dst = woh; }
    float4 v = *(const float4*)(src + (size_t)j * 4);
    __half2 H0, H1;
    H0.x = __float2half_rn(v.x); H0.y = __float2half_rn(v.y);
    H1.x = __float2half_rn(v.z); H1.y = __float2half_rn(v.w);
    ((__half2*)dst)[j * 2 + 0] = H0;
    ((__half2*)dst)[j * 2 + 1] = H1;
}

// ---------------------------------------------------------------------------
// MMA primitives
// ---------------------------------------------------------------------------
__device__ __forceinline__ void ldsm4(unsigned addr, unsigned& r0, unsigned& r1,
                                      unsigned& r2, unsigned& r3) {
    asm volatile("ldmatrix.sync.aligned.m8n8.x4.shared.b16 {%0,%1,%2,%3}, [%4];"
                 : "=r"(r0), "=r"(r1), "=r"(r2), "=r"(r3) : "r"(addr));
}
__device__ __forceinline__ void ldsm4t(unsigned addr, unsigned& r0, unsigned& r1,
                                       unsigned& r2, unsigned& r3) {
    asm volatile("ldmatrix.sync.aligned.m8n8.x4.trans.shared.b16 {%0,%1,%2,%3}, [%4];"
                 : "=r"(r0), "=r"(r1), "=r"(r2), "=r"(r3) : "r"(addr));
}
__device__ __forceinline__ void mma_fp(float* d, const unsigned* a,
                                       unsigned b0, unsigned b1) {
    asm volatile(
        "mma.sync.aligned.m16n8k16.row.col.f32.f16.f16.f32 "
        "{%0,%1,%2,%3}, {%4,%5,%6,%7}, {%8,%9}, {%0,%1,%2,%3};"
        : "+f"(d[0]), "+f"(d[1]), "+f"(d[2]), "+f"(d[3])
        : "r"(a[0]), "r"(a[1]), "r"(a[2]), "r"(a[3]), "r"(b0), "r"(b1));
}

// ---------------------------------------------------------------------------
// fp16 NT GEMM (fp32 accum): C = A @ B^T (+bias).
// 128x128 block, KC=64, 256 thr (8 warps, 2x4 of 64x32 warp tiles),
// 3-stage cp.async ring (issue depth 2, wait_group 1), 2 CTAs/SM,
// single __syncthreads per K-chunk.
// MODE 1: QKV epilogue (q scaled by QSC; q/k/v fp16 in [b,h,s,64]).
// MODE 2: fp32 C + bias.
// ---------------------------------------------------------------------------
#define KC 64
#define STAGE_BYTES 32768          // A 16K + B 16K
#define GM_SMEM (3 * STAGE_BYTES)  // 96KB -> 2 CTAs/SM (192KB)

template <int MODE>
__global__ __launch_bounds__(256, 2) void gemm2(
    const __half* __restrict__ Ahi, const __half* __restrict__ Bhi,
    const float* __restrict__ bias, float* __restrict__ C,
    __half* __restrict__ qh, __half* __restrict__ kh,
    __half* __restrict__ vh,
    int M, int N, int K)
{
    extern __shared__ __align__(1024) char sm[];
    const unsigned sb = smem_u32(sm);
    const int tid  = threadIdx.x;
    const int lane = tid & 31;
    const int wid  = tid >> 5;
    const int wm   = wid >> 2;
    const int wn   = wid & 3;
    const int m0   = blockIdx.y * 128;
    const int n0   = blockIdx.x * 128;

    const __half* src0 = Ahi + (size_t)m0 * K;
    const __half* src1 = Bhi + (size_t)n0 * K;

    const int lr0  = tid >> 3;
    const int lc16 = tid & 7;

    float acc[4][4][4];
#pragma unroll
    for (int i = 0; i < 4; i++)
#pragma unroll
        for (int j = 0; j < 4; j++)
#pragma unroll
            for (int q = 0; q < 4; q++) acc[i][j][q] = 0.f;

    const int nch = K / KC;

    auto issue = [&](int cc, int stg) {
        const int k0 = cc * KC;
        const unsigned sbase = sb + stg * STAGE_BYTES;
        const __half* srcs[2] = {src0, src1};
#pragma unroll
        for (int op = 0; op < 2; op++) {
            const __half* s = srcs[op];
            const unsigned dst = sbase + op * 16384;
#pragma unroll
            for (int it = 0; it < 4; it++) {
                int r = lr0 + it * 32;
                unsigned saddr = dst + r * 128 + ((lc16 * 16) ^ ((r & 7) << 4));
                const void* g = s + (size_t)r * K + k0 + lc16 * 8;
                asm volatile("cp.async.cg.shared.global [%0], [%1], 16;"
                             :: "r"(saddr), "l"(g));
            }
        }
        asm volatile("cp.async.commit_group;" ::: "memory");
    };

    issue(0, 0);
    if (nch > 1) issue(1, 1);

    const int arow = (lane & 15);
    const unsigned acb0 = (lane >> 4) * 16;
    const int bnr  = (lane & 7) + ((lane >> 4) << 3);
    const unsigned bcb0 = ((lane >> 3) & 1) * 16;

    for (int cc = 0; cc < nch; cc++) {
        // steady state: groups {cc, cc+1} pending -> wait 1 leaves cc+1
        if (cc + 1 < nch) {
            asm volatile("cp.async.wait_group 1;" ::: "memory");
        } else {
            asm volatile("cp.async.wait_group 0;" ::: "memory");
        }
        __syncthreads();   // stage cc visible; all warps done reading cc-1
        if (cc + 2 < nch) issue(cc + 2, (cc + 2) % 3);

        const unsigned sbase = sb + (cc % 3) * STAGE_BYTES;
        const unsigned Ah = sbase, Bb = sbase + 16384;

#pragma unroll
        for (int k16 = 0; k16 < 4; k16++) {
            unsigned ah[4][4];
#pragma unroll
            for (int mt = 0; mt < 4; mt++) {
                int r = wm * 64 + mt * 16 + arow;
                unsigned cb = k16 * 32 + acb0;
                unsigned off = r * 128 + (cb ^ ((r & 7) << 4));
                ldsm4(Ah + off, ah[mt][0], ah[mt][1], ah[mt][2], ah[mt][3]);
            }
            unsigned b[2][4];
#pragma unroll
            for (int bt = 0; bt < 2; bt++) {
                int n = wn * 32 + bt * 16 + bnr;
                unsigned cb = k16 * 32 + bcb0;
                unsigned addr = Bb + n * 128 + (cb ^ ((n & 7) << 4));
                ldsm4(addr, b[bt][0], b[bt][1], b[bt][2], b[bt][3]);
            }
#pragma unroll
            for (int mt = 0; mt < 4; mt++)
#pragma unroll
                for (int nt = 0; nt < 4; nt++)
                    mma_fp(acc[mt][nt], ah[mt],
                           b[nt >> 1][(nt & 1) * 2],
                           b[nt >> 1][(nt & 1) * 2 + 1]);
        }
    }

    // ---- epilogue ----
#pragma unroll
    for (int mt = 0; mt < 4; mt++) {
        int r0 = m0 + wm * 64 + mt * 16 + (lane >> 2);
#pragma unroll
        for (int nt = 0; nt < 4; nt++) {
            int c = n0 + wn * 32 + nt * 8 + (lane & 3) * 2;
            if (MODE == 2) {
                float2 bv = make_float2(0.f, 0.f);
                if (bias) bv = *(const float2*)(bias + c);
                *(float2*)(C + (size_t)r0 * N + c) =
                    make_float2(acc[mt][nt][0] + bv.x, acc[mt][nt][1] + bv.y);
                *(float2*)(C + (size_t)(r0 + 8) * N + c) =
                    make_float2(acc[mt][nt][2] + bv.x, acc[mt][nt][3] + bv.y);
            } else {
                int which = c >> 10;           // 0: v, 1: q, 2: k
                int rem   = c & 1023;
                int h     = rem >> 6;
                int d     = rem & 63;
                __half* dst = (which == 0) ? vh : (which == 1) ? qh : kh;
                const float sc = (which == 1) ? QSC : 1.f;
#pragma unroll
                for (int half_ = 0; half_ < 2; half_++) {
                    int row = r0 + half_ * 8;
                    float v0 = acc[mt][nt][half_ * 2 + 0] * sc;
                    float v1 = acc[mt][nt][half_ * 2 + 1] * sc;
                    int b = row >> 11, s = row & 2047;
                    size_t idx = ((size_t)(b * HH + h) * SS + s) * HDIM + d;
                    __half2 Hp;
                    Hp.x = __float2half_rn(v0);
                    Hp.y = __float2half_rn(v1);
                    *(__half2*)(dst + idx) = Hp;
                }
            }
        }
    }
}

// ---------------------------------------------------------------------------
// Tensor-core flash attention, uniform fp16 (fp32 accum).
// Softmax: ex2.approx.f16x2 P; l via ones-column MMA.
// 128 q rows/block, 8 warps, BK=64, 3-stage cp.async KV ring
// (issue depth 2, wait_group 1), 2 CTAs/SM.
// ---------------------------------------------------------------------------
#define FA_SMEM (16384 + 3 * 16384)   // Q + 3 KV stages = 64KB

__global__ __launch_bounds__(256, 2) void flash_mma(
    const __half* __restrict__ Qhi,
    const __half* __restrict__ Khi, const __half* __restrict__ Vhi,
    __half* __restrict__ Ohi)
{
    extern __shared__ __align__(1024) char sm[];
    const unsigned sb = smem_u32(sm);
    const int tid  = threadIdx.x;
    const int lane = tid & 31;
    const int wid  = tid >> 5;
    const int q0   = blockIdx.x * 128;
    const int bh   = blockIdx.y;

    const size_t base = (size_t)bh * SS * HDIM;
    const __half* qhg = Qhi + base;
    const __half* khg = Khi + base;
    const __half* vhg = Vhi + base;

    const unsigned sQh = sb;
    const unsigned sStage = sb + 16384;

    // ---- Q tile (128 x 64 fp16) ----
#pragma unroll
    for (int it = 0; it < 4; it++) {
        int idx = it * 256 + tid;
        int r   = idx >> 3;
        int c16 = idx & 7;
        unsigned off = r * 128 + ((c16 * 16) ^ ((r & 7) << 4));
        const void* gh = qhg + (size_t)(q0 + r) * HDIM + c16 * 8;
        asm volatile("cp.async.cg.shared.global [%0], [%1], 16;"
                     :: "r"(sQh + off), "l"(gh));
    }
    asm volatile("cp.async.commit_group;" ::: "memory");

    auto issue_kv = [&](int i, int stg) {
        const int kv0 = i * 64;
        const unsigned s0 = sStage + stg * 16384;
        const __half* srcs[2] = {khg, vhg};
#pragma unroll
        for (int op = 0; op < 2; op++) {
            const unsigned dst = s0 + op * 8192;
#pragma unroll
            for (int it = 0; it < 2; it++) {
                int idx = it * 256 + tid;
                int r   = idx >> 3;
                int c16 = idx & 7;
                unsigned saddr = dst + r * 128 + ((c16 * 16) ^ ((r & 7) << 4));
                const void* g = srcs[op] + (size_t)(kv0 + r) * HDIM + c16 * 8;
                asm volatile("cp.async.cg.shared.global [%0], [%1], 16;"
                             :: "r"(saddr), "l"(g));
            }
        }
        asm volatile("cp.async.commit_group;" ::: "memory");
    };

    issue_kv(0, 0);
    issue_kv(1, 1);
    // pending: {Q, kv0, kv1}; wait 2 -> Q complete
    asm volatile("cp.async.wait_group 2;" ::: "memory");
    __syncthreads();

    // ---- persistent Q a-frags ----
    unsigned qhf[4][4];
    {
        const int arow = wid * 16 + (lane & 15);
        const unsigned acb0 = (lane >> 4) * 16;
#pragma unroll
        for (int ks = 0; ks < 4; ks++) {
            unsigned cb = ks * 32 + acb0;
            unsigned off = arow * 128 + (cb ^ ((arow & 7) << 4));
            ldsm4(sQh + off, qhf[ks][0], qhf[ks][1], qhf[ks][2], qhf[ks][3]);
        }
    }

    float o[8][4];
#pragma unroll
    for (int i = 0; i < 8; i++)
#pragma unroll
        for (int j = 0; j < 4; j++) o[i][j] = 0.f;
    float lacc[4] = {0.f, 0.f, 0.f, 0.f};     // running l (ones-column MMA)
    float m0r = -1e30f, m1r = -1e30f;

    const int bnr  = (lane & 7) + ((lane >> 4) << 3);
    const unsigned bcb0 = ((lane >> 3) & 1) * 16;
    const int vrow0 = (lane & 7) + (((lane >> 3) & 1) << 3);
    const unsigned vcb = (lane >> 4) * 16;

    const int NIT = SS / 64;   // 32
    for (int cc = 0; cc < NIT; cc++) {
        if (cc + 1 < NIT) {
            asm volatile("cp.async.wait_group 1;" ::: "memory");
        } else {
            asm volatile("cp.async.wait_group 0;" ::: "memory");
        }
        __syncthreads();   // stage cc visible; all warps done reading cc-1
        if (cc + 2 < NIT) issue_kv(cc + 2, (cc + 2) % 3);

        const unsigned st = sStage + (cc % 3) * 16384;
        const unsigned sKh = st, sVh = st + 8192;

        // ---- S = Q K^T (exp2-domain logits) ----
        float s[8][4];
#pragma unroll
        for (int i = 0; i < 8; i++)
#pragma unroll
            for (int j = 0; j < 4; j++) s[i][j] = 0.f;

#pragma unroll
        for (int ks = 0; ks < 4; ks++) {
#pragma unroll
            for (int g = 0; g < 4; g++) {
                int r = g * 16 + bnr;
                unsigned cb = ks * 32 + bcb0;
                unsigned off = r * 128 + (cb ^ ((r & 7) << 4));
                unsigned h0, h1, h2, h3;
                ldsm4(sKh + off, h0, h1, h2, h3);
                mma_fp(s[2 * g],     qhf[ks], h0, h1);
                mma_fp(s[2 * g + 1], qhf[ks], h2, h3);
            }
        }

        // ---- online softmax: max reduction + rescale ----
        float mx0 = -1e30f, mx1 = -1e30f;
#pragma unroll
        for (int nt = 0; nt < 8; nt++) {
            mx0 = fmaxf(mx0, fmaxf(s[nt][0], s[nt][1]));
            mx1 = fmaxf(mx1, fmaxf(s[nt][2], s[nt][3]));
        }
        mx0 = fmaxf(mx0, __shfl_xor_sync(0xffffffffu, mx0, 1));
        mx0 = fmaxf(mx0, __shfl_xor_sync(0xffffffffu, mx0, 2));
        mx1 = fmaxf(mx1, __shfl_xor_sync(0xffffffffu, mx1, 1));
        mx1 = fmaxf(mx1, __shfl_xor_sync(0xffffffffu, mx1, 2));
        float mn0 = fmaxf(m0r, mx0), mn1 = fmaxf(m1r, mx1);
        float f0 = ex2(m0r - mn0), f1 = ex2(m1r - mn1);
        m0r = mn0; m1r = mn1;
#pragma unroll
        for (int nd = 0; nd < 8; nd++) {
            o[nd][0] *= f0; o[nd][1] *= f0;
            o[nd][2] *= f1; o[nd][3] *= f1;
        }
        lacc[0] *= f0; lacc[1] *= f0;
        lacc[2] *= f1; lacc[3] *= f1;

        // ---- P = exp2(s - m) via f16x2 MUFU; O += P V; l += P·1 ----
#pragma unroll
        for (int kk = 0; kk < 4; kk++) {
            unsigned pah[4];
            pah[0] = h2ex2(s[2 * kk][0] - mn0, s[2 * kk][1] - mn0);
            pah[1] = h2ex2(s[2 * kk][2] - mn1, s[2 * kk][3] - mn1);
            pah[2] = h2ex2(s[2 * kk + 1][0] - mn0, s[2 * kk + 1][1] - mn0);
            pah[3] = h2ex2(s[2 * kk + 1][2] - mn1, s[2 * kk + 1][3] - mn1);

            mma_fp(lacc, pah, ONESH2, ONESH2);   // row sums -> l

#pragma unroll
            for (int np = 0; np < 4; np++) {
                int r = kk * 16 + vrow0;
                unsigned cb = (np * 2) * 16 + vcb;
                unsigned off = r * 128 + (cb ^ ((r & 7) << 4));
                unsigned v0, v1, v2, v3;
                ldsm4t(sVh + off, v0, v1, v2, v3);
                mma_fp(o[2 * np],     pah, v0, v1);
                mma_fp(o[2 * np + 1], pah, v2, v3);
            }
        }
    }

    // ---- epilogue: normalize + write fp16 [4096][1024] ----
    const float inv0 = 1.f / lacc[0], inv1 = 1.f / lacc[2];
    const int b = bh >> 4, h = bh & 15;
    const int row0 = q0 + wid * 16 + (lane >> 2);
    const int grow0 = b * SS + row0;
    const int col0 = h * HDIM + (lane & 3) * 2;
#pragma unroll
    for (int nd = 0; nd < 8; nd++) {
        int c = col0 + nd * 8;
#pragma unroll
        for (int half_ = 0; half_ < 2; half_++) {
            float v0 = o[nd][half_ * 2 + 0] * (half_ ? inv1 : inv0);
            float v1 = o[nd][half_ * 2 + 1] * (half_ ? inv1 : inv0);
            size_t idx = (size_t)(grow0 + half_ * 8) * DD + c;
            __half2 Hp;
            Hp.x = __float2half_rn(v0);
            Hp.y = __float2half_rn(v1);
            *(__half2*)(Ohi + idx) = Hp;
        }
    }
}

// ---------------------------------------------------------------------------
extern "C" void kernel_launch(void* const* d_in, const int* in_sizes, int n_in,
                              void* d_out, int out_size)
{
    const float* x     = (const float*)d_in[0];
    const float* w_qkv = (const float*)d_in[1];
    const float* w_out = (const float*)d_in[2];
    const float* b_out = (const float*)d_in[3];
    float* out = (float*)d_out;

    void *xhi_p, *wqh_p, *woh_p, *ohi_p, *qh_p, *kh_p, *vh_p;
    cudaGetSymbolAddress(&xhi_p, g_xhi);
    cudaGetSymbolAddress(&wqh_p, g_wqh);
    cudaGetSymbolAddress(&woh_p, g_woh);
    cudaGetSymbolAddress(&ohi_p, g_ohi);
    cudaGetSymbolAddress(&qh_p, g_qh);
    cudaGetSymbolAddress(&kh_p, g_kh);
    cudaGetSymbolAddress(&vh_p, g_vh);

    cudaFuncSetAttribute(gemm2<1>,
                         cudaFuncAttributeMaxDynamicSharedMemorySize, GM_SMEM);
    cudaFuncSetAttribute(gemm2<2>,
                         cudaFuncAttributeMaxDynamicSharedMemorySize, GM_SMEM);
    cudaFuncSetAttribute(flash_mma,
                         cudaFuncAttributeMaxDynamicSharedMemorySize, FA_SMEM);

    // 0) fused fp16 conversions
    split_all<<<(N4TOT + 255) / 256, 256>>>(
        x, w_qkv, w_out,
        (__half*)xhi_p, (__half*)wqh_p, (__half*)woh_p);

    // 1) QKV projection -> q (scaled by SCALE*log2e), k, v fp16 [b,h,s,64]
    dim3 g1(QKV_E / 128, MROWS / 128);
    gemm2<1><<<g1, 256, GM_SMEM>>>(
        (const __half*)xhi_p, (const __half*)wqh_p,
        nullptr, nullptr,
        (__half*)qh_p, (__half*)kh_p, (__half*)vh_p,
        MROWS, QKV_E, DD);

    // 2) flash attention -> o fp16
    dim3 g2(SS / 128, BB * HH);
    flash_mma<<<g2, 256, FA_SMEM>>>(
        (const __half*)qh_p, (const __half*)kh_p, (const __half*)vh_p,
        (__half*)ohi_p);

    // 3) output projection with bias -> fp32 out
    dim3 g3(DD / 128, MROWS / 128);
    gemm2<2><<<g3, 256, GM_SMEM>>>(
        (const __half*)ohi_p, (const __half*)woh_p,
        b_out, out,
        nullptr, nullptr, nullptr,
        MROWS, DD, DD);
}

// round 15
// speedup vs baseline: 1.0906x; 1.0906x over previous
#include <cuda_runtime.h>
#include <cuda_fp16.h>

// Problem constants
#define BB   2
#define SS   2048
#define DD   1024
#define HH   16
#define HDIM 64
#define MROWS (BB * SS)           // 4096
#define QKV_E (3 * DD)            // 3072
#define SCALE 0.125f              // 1/sqrt(64)
#define QSC   (0.125f * 1.4426950408889634f)   // SCALE * log2(e)
#define ONESH2 0x3C003C00u        // half2(1.0, 1.0)

// Scratch (device globals per harness allocation rules)
__device__ __align__(16) __half g_xhi[MROWS * DD];
__device__ __align__(16) __half g_wqh[QKV_E * DD];
__device__ __align__(16) __half g_woh[DD * DD];
__device__ __align__(16) __half g_ohi[MROWS * DD];
#define QKVN (BB * HH * SS * HDIM)
__device__ __align__(16) __half g_qh[QKVN];
__device__ __align__(16) __half g_kh[QKVN];
__device__ __align__(16) __half g_vh[QKVN];

__device__ __forceinline__ unsigned smem_u32(const void* p) {
    unsigned a;
    asm("{ .reg .u64 t; cvta.to.shared.u64 t, %1; cvt.u32.u64 %0, t; }"
        : "=r"(a) : "l"(p));
    return a;
}
__device__ __forceinline__ float ex2(float x) {
    float r;
    asm("ex2.approx.f32 %0, %1;" : "=f"(r) : "f"(x));
    return r;
}
// half2 exp2 of packed (a,b) -> single MUFU op
__device__ __forceinline__ unsigned h2ex2(float a, float b) {
    __half2 t = __floats2half2_rn(a, b);
    unsigned r;
    asm("ex2.approx.f16x2 %0, %1;" : "=r"(r) : "r"(*(unsigned*)&t));
    return r;
}

// ---------------------------------------------------------------------------
// Fused splits: x, w_qkv, w_out -> fp16 (round-to-nearest)
// ---------------------------------------------------------------------------
#define N4X (MROWS * DD / 4)      // 1048576
#define N4Q (QKV_E * DD / 4)      // 786432
#define N4W (DD * DD / 4)         // 262144
#define N4TOT (N4X + N4Q + N4W)   // 2097152

__global__ __launch_bounds__(256) void split_all(
    const float* __restrict__ x, const float* __restrict__ wq,
    const float* __restrict__ wo,
    __half* __restrict__ xhi, __half* __restrict__ wqh,
    __half* __restrict__ woh)
{
    int i = blockIdx.x * blockDim.x + threadIdx.x;
    if (i >= N4TOT) return;
    const float* src;
    __half* dst;
    int j;
    if (i < N4X)            { j = i;             src = x;  dst = xhi; }
    else if (i < N4X + N4Q) { j = i - N4X;       src = wq; dst = wqh; }
    else                    { j = i - N4X - N4Q; src = wo; dst = woh; }
    float4 v = *(const float4*)(src + (size_t)j * 4);
    __half2 H0, H1;
    H0.x = __float2half_rn(v.x); H0.y = __float2half_rn(v.y);
    H1.x = __float2half_rn(v.z); H1.y = __float2half_rn(v.w);
    ((__half2*)dst)[j * 2 + 0] = H0;
    ((__half2*)dst)[j * 2 + 1] = H1;
}

// ---------------------------------------------------------------------------
// MMA primitives
// ---------------------------------------------------------------------------
__device__ __forceinline__ void ldsm4(unsigned addr, unsigned& r0, unsigned& r1,
                                      unsigned& r2, unsigned& r3) {
    asm volatile("ldmatrix.sync.aligned.m8n8.x4.shared.b16 {%0,%1,%2,%3}, [%4];"
                 : "=r"(r0), "=r"(r1), "=r"(r2), "=r"(r3) : "r"(addr));
}
__device__ __forceinline__ void ldsm4t(unsigned addr, unsigned& r0, unsigned& r1,
                                       unsigned& r2, unsigned& r3) {
    asm volatile("ldmatrix.sync.aligned.m8n8.x4.trans.shared.b16 {%0,%1,%2,%3}, [%4];"
                 : "=r"(r0), "=r"(r1), "=r"(r2), "=r"(r3) : "r"(addr));
}
__device__ __forceinline__ void mma_fp(float* d, const unsigned* a,
                                       unsigned b0, unsigned b1) {
    asm volatile(
        "mma.sync.aligned.m16n8k16.row.col.f32.f16.f16.f32 "
        "{%0,%1,%2,%3}, {%4,%5,%6,%7}, {%8,%9}, {%0,%1,%2,%3};"
        : "+f"(d[0]), "+f"(d[1]), "+f"(d[2]), "+f"(d[3])
        : "r"(a[0]), "r"(a[1]), "r"(a[2]), "r"(a[3]), "r"(b0), "r"(b1));
}

// ---------------------------------------------------------------------------
// fp16 NT GEMM (fp32 accum): C = A @ B^T (+bias).
// 128x128 block, KC=64, 256 thr (8 warps, 2x4 of 64x32 warp tiles),
// 2-stage cp.async, 2 CTAs/SM, single __syncthreads per K-chunk.
// (R13 configuration — 3-stage ring measured neutral, reverted.)
// MODE 1: QKV epilogue (q scaled by QSC; q/k/v fp16 in [b,h,s,64]).
// MODE 2: fp32 C + bias.
// ---------------------------------------------------------------------------
#define KC 64
#define STAGE_BYTES 32768          // A 16K + B 16K
#define GM_SMEM (2 * STAGE_BYTES)  // 64KB -> 2 CTAs/SM

template <int MODE>
__global__ __launch_bounds__(256, 2) void gemm2(
    const __half* __restrict__ Ahi, const __half* __restrict__ Bhi,
    const float* __restrict__ bias, float* __restrict__ C,
    __half* __restrict__ qh, __half* __restrict__ kh,
    __half* __restrict__ vh,
    int M, int N, int K)
{
    extern __shared__ __align__(1024) char sm[];
    const unsigned sb = smem_u32(sm);
    const int tid  = threadIdx.x;
    const int lane = tid & 31;
    const int wid  = tid >> 5;
    const int wm   = wid >> 2;
    const int wn   = wid & 3;
    const int m0   = blockIdx.y * 128;
    const int n0   = blockIdx.x * 128;

    const __half* src0 = Ahi + (size_t)m0 * K;
    const __half* src1 = Bhi + (size_t)n0 * K;

    const int lr0  = tid >> 3;
    const int lc16 = tid & 7;

    float acc[4][4][4];
#pragma unroll
    for (int i = 0; i < 4; i++)
#pragma unroll
        for (int j = 0; j < 4; j++)
#pragma unroll
            for (int q = 0; q < 4; q++) acc[i][j][q] = 0.f;

    const int nch = K / KC;

    auto issue = [&](int cc, int stg) {
        const int k0 = cc * KC;
        const unsigned sbase = sb + stg * STAGE_BYTES;
        const __half* srcs[2] = {src0, src1};
#pragma unroll
        for (int op = 0; op < 2; op++) {
            const __half* s = srcs[op];
            const unsigned dst = sbase + op * 16384;
#pragma unroll
            for (int it = 0; it < 4; it++) {
                int r = lr0 + it * 32;
                unsigned saddr = dst + r * 128 + ((lc16 * 16) ^ ((r & 7) << 4));
                const void* g = s + (size_t)r * K + k0 + lc16 * 8;
                asm volatile("cp.async.cg.shared.global [%0], [%1], 16;"
                             :: "r"(saddr), "l"(g));
            }
        }
        asm volatile("cp.async.commit_group;" ::: "memory");
    };

    issue(0, 0);

    const int arow = (lane & 15);
    const unsigned acb0 = (lane >> 4) * 16;
    const int bnr  = (lane & 7) + ((lane >> 4) << 3);
    const unsigned bcb0 = ((lane >> 3) & 1) * 16;

    for (int cc = 0; cc < nch; cc++) {
        asm volatile("cp.async.wait_group 0;" ::: "memory");
        __syncthreads();   // stage cc visible; all warps done reading cc-1
        if (cc + 1 < nch) issue(cc + 1, (cc + 1) & 1);

        const unsigned sbase = sb + (cc & 1) * STAGE_BYTES;
        const unsigned Ah = sbase, Bb = sbase + 16384;

#pragma unroll
        for (int k16 = 0; k16 < 4; k16++) {
            unsigned ah[4][4];
#pragma unroll
            for (int mt = 0; mt < 4; mt++) {
                int r = wm * 64 + mt * 16 + arow;
                unsigned cb = k16 * 32 + acb0;
                unsigned off = r * 128 + (cb ^ ((r & 7) << 4));
                ldsm4(Ah + off, ah[mt][0], ah[mt][1], ah[mt][2], ah[mt][3]);
            }
            unsigned b[2][4];
#pragma unroll
            for (int bt = 0; bt < 2; bt++) {
                int n = wn * 32 + bt * 16 + bnr;
                unsigned cb = k16 * 32 + bcb0;
                unsigned addr = Bb + n * 128 + (cb ^ ((n & 7) << 4));
                ldsm4(addr, b[bt][0], b[bt][1], b[bt][2], b[bt][3]);
            }
#pragma unroll
            for (int mt = 0; mt < 4; mt++)
#pragma unroll
                for (int nt = 0; nt < 4; nt++)
                    mma_fp(acc[mt][nt], ah[mt],
                           b[nt >> 1][(nt & 1) * 2],
                           b[nt >> 1][(nt & 1) * 2 + 1]);
        }
    }

    // ---- epilogue ----
#pragma unroll
    for (int mt = 0; mt < 4; mt++) {
        int r0 = m0 + wm * 64 + mt * 16 + (lane >> 2);
#pragma unroll
        for (int nt = 0; nt < 4; nt++) {
            int c = n0 + wn * 32 + nt * 8 + (lane & 3) * 2;
            if (MODE == 2) {
                float2 bv = make_float2(0.f, 0.f);
                if (bias) bv = *(const float2*)(bias + c);
                *(float2*)(C + (size_t)r0 * N + c) =
                    make_float2(acc[mt][nt][0] + bv.x, acc[mt][nt][1] + bv.y);
                *(float2*)(C + (size_t)(r0 + 8) * N + c) =
                    make_float2(acc[mt][nt][2] + bv.x, acc[mt][nt][3] + bv.y);
            } else {
                int which = c >> 10;           // 0: v, 1: q, 2: k
                int rem   = c & 1023;
                int h     = rem >> 6;
                int d     = rem & 63;
                __half* dst = (which == 0) ? vh : (which == 1) ? qh : kh;
                const float sc = (which == 1) ? QSC : 1.f;
#pragma unroll
                for (int half_ = 0; half_ < 2; half_++) {
                    int row = r0 + half_ * 8;
                    float v0 = acc[mt][nt][half_ * 2 + 0] * sc;
                    float v1 = acc[mt][nt][half_ * 2 + 1] * sc;
                    int b = row >> 11, s = row & 2047;
                    size_t idx = ((size_t)(b * HH + h) * SS + s) * HDIM + d;
                    __half2 Hp;
                    Hp.x = __float2half_rn(v0);
                    Hp.y = __float2half_rn(v1);
                    *(__half2*)(dst + idx) = Hp;
                }
            }
        }
    }
}

// ---------------------------------------------------------------------------
// Tensor-core flash attention, uniform fp16 (fp32 accum).
// BQ=64: 128 threads (4 warps x 16 q-rows), 4 CTAs/SM -> fine-grained
// wave balance (1024 CTAs, quantum = 1/4 CTA-round). Per-warp shape is
// identical to the previous BQ=128 kernel.
// Softmax: ex2.approx.f16x2 P; l via ones-column MMA. 2-stage KV ring.
// ---------------------------------------------------------------------------
#define FA_SMEM (8192 + 2 * 16384)   // Q 8KB + 2 KV stages = 40KB

__global__ __launch_bounds__(128, 4) void flash_mma(
    const __half* __restrict__ Qhi,
    const __half* __restrict__ Khi, const __half* __restrict__ Vhi,
    __half* __restrict__ Ohi)
{
    extern __shared__ __align__(1024) char sm[];
    const unsigned sb = smem_u32(sm);
    const int tid  = threadIdx.x;
    const int lane = tid & 31;
    const int wid  = tid >> 5;          // 0..3
    const int q0   = blockIdx.x * 64;
    const int bh   = blockIdx.y;

    const size_t base = (size_t)bh * SS * HDIM;
    const __half* qhg = Qhi + base;
    const __half* khg = Khi + base;
    const __half* vhg = Vhi + base;

    const unsigned sQh = sb;
    const unsigned sStage = sb + 8192;

    // ---- Q tile (64 x 64 fp16) ----
#pragma unroll
    for (int it = 0; it < 4; it++) {
        int idx = it * 128 + tid;          // 0..511
        int r   = idx >> 3;                // 0..63
        int c16 = idx & 7;
        unsigned off = r * 128 + ((c16 * 16) ^ ((r & 7) << 4));
        const void* gh = qhg + (size_t)(q0 + r) * HDIM + c16 * 8;
        asm volatile("cp.async.cg.shared.global [%0], [%1], 16;"
                     :: "r"(sQh + off), "l"(gh));
    }
    asm volatile("cp.async.commit_group;" ::: "memory");

    auto issue_kv = [&](int i, int stg) {
        const int kv0 = i * 64;
        const unsigned s0 = sStage + stg * 16384;
        const __half* srcs[2] = {khg, vhg};
#pragma unroll
        for (int op = 0; op < 2; op++) {
            const unsigned dst = s0 + op * 8192;
#pragma unroll
            for (int it = 0; it < 4; it++) {
                int idx = it * 128 + tid;  // 0..511
                int r   = idx >> 3;        // 0..63
                int c16 = idx & 7;
                unsigned saddr = dst + r * 128 + ((c16 * 16) ^ ((r & 7) << 4));
                const void* g = srcs[op] + (size_t)(kv0 + r) * HDIM + c16 * 8;
                asm volatile("cp.async.cg.shared.global [%0], [%1], 16;"
                             :: "r"(saddr), "l"(g));
            }
        }
        asm volatile("cp.async.commit_group;" ::: "memory");
    };

    issue_kv(0, 0);
    asm volatile("cp.async.wait_group 0;" ::: "memory");   // Q + kv0 done
    __syncthreads();

    // ---- persistent Q a-frags ----
    unsigned qhf[4][4];
    {
        const int arow = wid * 16 + (lane & 15);
        const unsigned acb0 = (lane >> 4) * 16;
#pragma unroll
        for (int ks = 0; ks < 4; ks++) {
            unsigned cb = ks * 32 + acb0;
            unsigned off = arow * 128 + (cb ^ ((arow & 7) << 4));
            ldsm4(sQh + off, qhf[ks][0], qhf[ks][1], qhf[ks][2], qhf[ks][3]);
        }
    }

    float o[8][4];
#pragma unroll
    for (int i = 0; i < 8; i++)
#pragma unroll
        for (int j = 0; j < 4; j++) o[i][j] = 0.f;
    float lacc[4] = {0.f, 0.f, 0.f, 0.f};     // running l (ones-column MMA)
    float m0r = -1e30f, m1r = -1e30f;

    const int bnr  = (lane & 7) + ((lane >> 4) << 3);
    const unsigned bcb0 = ((lane >> 3) & 1) * 16;
    const int vrow0 = (lane & 7) + (((lane >> 3) & 1) << 3);
    const unsigned vcb = (lane >> 4) * 16;

    const int NIT = SS / 64;   // 32
    for (int cc = 0; cc < NIT; cc++) {
        asm volatile("cp.async.wait_group 0;" ::: "memory");
        __syncthreads();
        if (cc + 1 < NIT) issue_kv(cc + 1, (cc + 1) & 1);

        const unsigned st = sStage + (cc & 1) * 16384;
        const unsigned sKh = st, sVh = st + 8192;

        // ---- S = Q K^T (exp2-domain logits) ----
        float s[8][4];
#pragma unroll
        for (int i = 0; i < 8; i++)
#pragma unroll
            for (int j = 0; j < 4; j++) s[i][j] = 0.f;

#pragma unroll
        for (int ks = 0; ks < 4; ks++) {
#pragma unroll
            for (int g = 0; g < 4; g++) {
                int r = g * 16 + bnr;
                unsigned cb = ks * 32 + bcb0;
                unsigned off = r * 128 + (cb ^ ((r & 7) << 4));
                unsigned h0, h1, h2, h3;
                ldsm4(sKh + off, h0, h1, h2, h3);
                mma_fp(s[2 * g],     qhf[ks], h0, h1);
                mma_fp(s[2 * g + 1], qhf[ks], h2, h3);
            }
        }

        // ---- online softmax: max reduction + rescale ----
        float mx0 = -1e30f, mx1 = -1e30f;
#pragma unroll
        for (int nt = 0; nt < 8; nt++) {
            mx0 = fmaxf(mx0, fmaxf(s[nt][0], s[nt][1]));
            mx1 = fmaxf(mx1, fmaxf(s[nt][2], s[nt][3]));
        }
        mx0 = fmaxf(mx0, __shfl_xor_sync(0xffffffffu, mx0, 1));
        mx0 = fmaxf(mx0, __shfl_xor_sync(0xffffffffu, mx0, 2));
        mx1 = fmaxf(mx1, __shfl_xor_sync(0xffffffffu, mx1, 1));
        mx1 = fmaxf(mx1, __shfl_xor_sync(0xffffffffu, mx1, 2));
        float mn0 = fmaxf(m0r, mx0), mn1 = fmaxf(m1r, mx1);
        float f0 = ex2(m0r - mn0), f1 = ex2(m1r - mn1);
        m0r = mn0; m1r = mn1;
#pragma unroll
        for (int nd = 0; nd < 8; nd++) {
            o[nd][0] *= f0; o[nd][1] *= f0;
            o[nd][2] *= f1; o[nd][3] *= f1;
        }
        lacc[0] *= f0; lacc[1] *= f0;
        lacc[2] *= f1; lacc[3] *= f1;

        // ---- P = exp2(s - m) via f16x2 MUFU; O += P V; l += P·1 ----
#pragma unroll
        for (int kk = 0; kk < 4; kk++) {
            unsigned pah[4];
            pah[0] = h2ex2(s[2 * kk][0] - mn0, s[2 * kk][1] - mn0);
            pah[1] = h2ex2(s[2 * kk][2] - mn1, s[2 * kk][3] - mn1);
            pah[2] = h2ex2(s[2 * kk + 1][0] - mn0, s[2 * kk + 1][1] - mn0);
            pah[3] = h2ex2(s[2 * kk + 1][2] - mn1, s[2 * kk + 1][3] - mn1);

            mma_fp(lacc, pah, ONESH2, ONESH2);   // row sums -> l

#pragma unroll
            for (int np = 0; np < 4; np++) {
                int r = kk * 16 + vrow0;
                unsigned cb = (np * 2) * 16 + vcb;
                unsigned off = r * 128 + (cb ^ ((r & 7) << 4));
                unsigned v0, v1, v2, v3;
                ldsm4t(sVh + off, v0, v1, v2, v3);
                mma_fp(o[2 * np],     pah, v0, v1);
                mma_fp(o[2 * np + 1], pah, v2, v3);
            }
        }
    }

    // ---- epilogue: normalize + write fp16 [4096][1024] ----
    const float inv0 = 1.f / lacc[0], inv1 = 1.f / lacc[2];
    const int b = bh >> 4, h = bh & 15;
    const int row0 = q0 + wid * 16 + (lane >> 2);
    const int grow0 = b * SS + row0;
    const int col0 = h * HDIM + (lane & 3) * 2;
#pragma unroll
    for (int nd = 0; nd < 8; nd++) {
        int c = col0 + nd * 8;
#pragma unroll
        for (int half_ = 0; half_ < 2; half_++) {
            float v0 = o[nd][half_ * 2 + 0] * (half_ ? inv1 : inv0);
            float v1 = o[nd][half_ * 2 + 1] * (half_ ? inv1 : inv0);
            size_t idx = (size_t)(grow0 + half_ * 8) * DD + c;
            __half2 Hp;
            Hp.x = __float2half_rn(v0);
            Hp.y = __float2half_rn(v1);
            *(__half2*)(Ohi + idx) = Hp;
        }
    }
}

// ---------------------------------------------------------------------------
extern "C" void kernel_launch(void* const* d_in, const int* in_sizes, int n_in,
                              void* d_out, int out_size)
{
    const float* x     = (const float*)d_in[0];
    const float* w_qkv = (const float*)d_in[1];
    const float* w_out = (const float*)d_in[2];
    const float* b_out = (const float*)d_in[3];
    float* out = (float*)d_out;

    void *xhi_p, *wqh_p, *woh_p, *ohi_p, *qh_p, *kh_p, *vh_p;
    cudaGetSymbolAddress(&xhi_p, g_xhi);
    cudaGetSymbolAddress(&wqh_p, g_wqh);
    cudaGetSymbolAddress(&woh_p, g_woh);
    cudaGetSymbolAddress(&ohi_p, g_ohi);
    cudaGetSymbolAddress(&qh_p, g_qh);
    cudaGetSymbolAddress(&kh_p, g_kh);
    cudaGetSymbolAddress(&vh_p, g_vh);

    cudaFuncSetAttribute(gemm2<1>,
                         cudaFuncAttributeMaxDynamicSharedMemorySize, GM_SMEM);
    cudaFuncSetAttribute(gemm2<2>,
                         cudaFuncAttributeMaxDynamicSharedMemorySize, GM_SMEM);
    cudaFuncSetAttribute(flash_mma,
                         cudaFuncAttributeMaxDynamicSharedMemorySize, FA_SMEM);

    // 0) fused fp16 conversions
    split_all<<<(N4TOT + 255) / 256, 256>>>(
        x, w_qkv, w_out,
        (__half*)xhi_p, (__half*)wqh_p, (__half*)woh_p);

    // 1) QKV projection -> q (scaled by SCALE*log2e), k, v fp16 [b,h,s,64]
    dim3 g1(QKV_E / 128, MROWS / 128);
    gemm2<1><<<g1, 256, GM_SMEM>>>(
        (const __half*)xhi_p, (const __half*)wqh_p,
        nullptr, nullptr,
        (__half*)qh_p, (__half*)kh_p, (__half*)vh_p,
        MROWS, QKV_E, DD);

    // 2) flash attention (BQ=64, 4 CTAs/SM) -> o fp16
    dim3 g2(SS / 64, BB * HH);
    flash_mma<<<g2, 128, FA_SMEM>>>(
        (const __half*)qh_p, (const __half*)kh_p, (const __half*)vh_p,
        (__half*)ohi_p);

    // 3) output projection with bias -> fp32 out
    dim3 g3(DD / 128, MROWS / 128);
    gemm2<2><<<g3, 256, GM_SMEM>>>(
        (const __half*)ohi_p, (const __half*)woh_p,
        b_out, out,
        nullptr, nullptr, nullptr,
        MROWS, DD, DD);
}